// round 6
// baseline (speedup 1.0000x reference)
#include <cuda_runtime.h>
#include <math.h>
#include <stdint.h>

#define Bb 32
#define Nn 64
#define Dd 256
#define PEN 10000.0f
#define INV_TEMP 20.0f   // 1/0.05

typedef unsigned long long u64;

// ---------------- device scratch (no allocations allowed) ----------------
__device__ float g_A  [Bb*Nn*Dd];   // s_t  @ W1a                   (2 MB)
__device__ float g_Bm [Bb*Nn*Dd];   // s_t1 @ W1b + b1              (2 MB)
__device__ float g_s1T[Bb*Dd*Nn];   // clipped s_t1 transposed [b][k][j] (2 MB)
__device__ float g_la [Bb*Nn*Nn];   // log_alpha                    (512 KB)

__device__ __forceinline__ float clip50(float x){ return fminf(fmaxf(x, -50.f), 50.f); }

__device__ __forceinline__ u64 pack2(float x, float y){
    u64 r; asm("mov.b64 %0, {%1, %2};" : "=l"(r) : "f"(x), "f"(y)); return r;
}
__device__ __forceinline__ void unpack2(u64 v, float &lo, float &hi){
    asm("mov.b64 {%0, %1}, %2;" : "=f"(lo), "=f"(hi) : "l"(v));
}
__device__ __forceinline__ void fma2(u64 &acc, u64 a, u64 b){
    asm("fma.rn.f32x2 %0, %1, %2, %0;" : "+l"(acc) : "l"(a), "l"(b));
}
__device__ __forceinline__ u64 fma2r(u64 a, u64 b, u64 c){
    u64 d; asm("fma.rn.f32x2 %0, %1, %2, %3;" : "=l"(d) : "l"(a), "l"(b), "l"(c)); return d;
}
__device__ __forceinline__ u64 lds64(const float* p){
    return *reinterpret_cast<const u64*>(p);
}
__device__ __forceinline__ void cp_async16(uint32_t dst, const void* src){
    asm volatile("cp.async.ca.shared.global [%0], [%1], 16;" :: "r"(dst), "l"(src));
}
#define CP_COMMIT() asm volatile("cp.async.commit_group;")
#define CP_WAIT2()  asm volatile("cp.async.wait_group 2;")
#define CP_WAIT1()  asm volatile("cp.async.wait_group 1;")
#define CP_WAIT0()  asm volatile("cp.async.wait_group 0;")

// ================= Kernel 1: A = clip(s_t)@W1a ; Bm = clip(s_t1)@W1b + b1 ============
// De-packed: s-tiles stored as duplicated (s,s) u64; W read as contiguous c-pairs.
// grid (4,B), 512 threads. Thread = (c-pair cp = tid&127, rows rb=(tid>>7)*4 .. +3).
#define P_S0D 0                 // u64 [256][17]  (8704 floats)
#define P_S1D 8704              // u64 [256][17]
#define P_WT  17408             // [2 stages][16384 floats]  (32 k x 256 c x 2 mats)
#define P_SMEM_FLOATS (17408 + 32768)
#define P_SMEM_BYTES  (P_SMEM_FLOATS*4)   // 200704

__global__ void __launch_bounds__(512, 1) precompute_kernel(
    const float* __restrict__ slots_t, const float* __restrict__ slots_t1,
    const float* __restrict__ W1, const float* __restrict__ b1)
{
    extern __shared__ float psm[];
    u64* S0D = reinterpret_cast<u64*>(psm + P_S0D);   // [k][r] stride 17 -> (k*17+r)
    u64* S1D = reinterpret_cast<u64*>(psm + P_S1D);
    float* WT = psm + P_WT;
    const u64* WTu = reinterpret_cast<const u64*>(WT);
    const int ig = blockIdx.x, b = blockIdx.y;
    const int tid = threadIdx.x;
    const int rowbase = b*Nn + ig*16;
    const int gbase = rowbase * Dd;
    const uint32_t wt_smem = (uint32_t)__cvta_generic_to_shared(WT);

    // prefetch W stages 0 and 1 (each: 32 k-rows of W1a + 32 of W1b = 64KB)
    #pragma unroll
    for (int t = 0; t < 2; t++){
        #pragma unroll
        for (int u = 0; u < 4; u++){
            int off = u*8192 + tid*16;
            cp_async16(wt_smem + t*65536 + off,         (const char*)(W1 + t*32*Dd) + off);
            cp_async16(wt_smem + t*65536 + 32768 + off, (const char*)(W1 + (256 + t*32)*Dd) + off);
        }
        CP_COMMIT();
    }

    // fill duplicated s-tiles (coalesced global reads: k fast)
    #pragma unroll
    for (int n = 0; n < 8; n++){
        int idx = tid + n*512;
        int r = idx >> 8, k = idx & 255;
        float v0 = clip50(slots_t [gbase + idx]);
        float v1 = clip50(slots_t1[gbase + idx]);
        S0D[k*17 + r] = pack2(v0, v0);
        S1D[k*17 + r] = pack2(v1, v1);
    }
    __syncthreads();

    // write g_s1T [b][k][j]  (j = ig*16 + r); r fast for semi-coalesced global writes
    #pragma unroll
    for (int n = 0; n < 8; n++){
        int idx = tid + n*512;
        int r = idx & 15, k = idx >> 4;
        float v = *reinterpret_cast<const float*>(&S1D[k*17 + r]);   // low half
        g_s1T[(b*256 + k)*64 + ig*16 + r] = v;
    }

    const int cp = tid & 127;           // c-pair: c = 2cp, 2cp+1
    const int rb = (tid >> 7) * 4;      // 4 local rows
    u64 accA[4], accB[4];
    #pragma unroll
    for (int p=0;p<4;p++){ accA[p]=0ULL; accB[p]=0ULL; }

    for (int t = 0; t < 8; t++){
        if (t < 7) { CP_WAIT1(); } else { CP_WAIT0(); }
        __syncthreads();
        const u64* WS = WTu + (t&1)*8192;          // stage base (u64 units)
        #pragma unroll 8
        for (int kk = 0; kk < 32; kk++){
            const int k = t*32 + kk;
            u64 wA = WS[kk*128 + cp];              // (W1a[k][2cp], W1a[k][2cp+1])
            u64 wB = WS[4096 + kk*128 + cp];       // (W1b[k][2cp], W1b[k][2cp+1])
            #pragma unroll
            for (int p=0;p<4;p++){
                fma2(accA[p], S0D[k*17 + rb + p], wA);
                fma2(accB[p], S1D[k*17 + rb + p], wB);
            }
        }
        __syncthreads();
        if (t + 2 < 8){
            const int tn = t + 2;
            #pragma unroll
            for (int u = 0; u < 4; u++){
                int off = u*8192 + tid*16;
                cp_async16(wt_smem + (tn&1)*65536 + off,         (const char*)(W1 + tn*32*Dd) + off);
                cp_async16(wt_smem + (tn&1)*65536 + 32768 + off, (const char*)(W1 + (256 + tn*32)*Dd) + off);
            }
            CP_COMMIT();
        }
    }

    const float2 b1p = *reinterpret_cast<const float2*>(&b1[2*cp]);
    #pragma unroll
    for (int p=0;p<4;p++){
        float lo, hi;
        unpack2(accA[p], lo, hi);
        *reinterpret_cast<float2*>(&g_A[(rowbase + rb + p)*Dd + 2*cp]) = make_float2(lo, hi);
        unpack2(accB[p], lo, hi);
        *reinterpret_cast<float2*>(&g_Bm[(rowbase + rb + p)*Dd + 2*cp]) = make_float2(lo + b1p.x, hi + b1p.y);
    }
}

// ================= Kernel 2: per (b,i) scores for all j -> log_alpha ===============
// De-packed GEMM1: DD stores duplicated (d,d); weights as contiguous c-pairs.
#define SOFF_ST1T 0        // u64 [256][32] (16384 floats); later W2P u64[128][64]
#define SOFF_H    16384    // [64][256]
#define SOFF_SCR  32768    // 2 x [16][256] W1c ping-pong (8192 floats); later H2 [64][64]
#define SOFF_DD   40960    // u64 [2][16][64] duplicated (4096 floats)
#define SOFF_STIP 45056    // u64 [256] (a,a)
#define SOFF_AB   45568    // [256]
#define SOFF_W3   45824    // [64]
#define SOFF_B2   45888    // [64]
#define S_SMEM_FLOATS 45952
#define S_SMEM_BYTES  (S_SMEM_FLOATS*4)   // 183808

__global__ void __launch_bounds__(512, 1) score_kernel(
    const float* __restrict__ slots_t,
    const float* __restrict__ alive_t, const float* __restrict__ alive_t1,
    const float* __restrict__ W1,
    const float* __restrict__ W2, const float* __restrict__ b2,
    const float* __restrict__ W3, const float* __restrict__ b3)
{
    extern __shared__ float sm[];
    float* H    = sm + SOFF_H;
    float* SCR  = sm + SOFF_SCR;
    float* AB   = sm + SOFF_AB;
    float* W3S  = sm + SOFF_W3;
    float* B2S  = sm + SOFF_B2;
    u64* ST1Tu = reinterpret_cast<u64*>(sm + SOFF_ST1T);
    u64* SCRu  = reinterpret_cast<u64*>(sm + SOFF_SCR);
    u64* DDu   = reinterpret_cast<u64*>(sm + SOFF_DD);
    u64* STIPu = reinterpret_cast<u64*>(sm + SOFF_STIP);

    const int i = blockIdx.x, b = blockIdx.y;
    const int tid = threadIdx.x;
    const int tx = tid & 31, w = tid >> 5;
    const int jb = w * 4;                     // warp owns j = jb..jb+3

    const uint32_t st1t_smem = (uint32_t)__cvta_generic_to_shared(sm + SOFF_ST1T);
    const uint32_t scr_smem  = (uint32_t)__cvta_generic_to_shared(SCR);
    const float* W1c = W1 + 512*Dd;
    const float* s1Tsrc = g_s1T + b*16384;

    // ---- prologue cp.async: ST1T (G0), W1c tile0 (G1), tile1 (G2) ----
    #pragma unroll
    for (int u = 0; u < 8; u++){
        int off = u*8192 + tid*16;
        cp_async16(st1t_smem + off, (const char*)s1Tsrc + off);
    }
    CP_COMMIT();
    #pragma unroll
    for (int u = 0; u < 2; u++){
        int off = u*8192 + tid*16;
        cp_async16(scr_smem + off, (const char*)W1c + off);
    }
    CP_COMMIT();
    #pragma unroll
    for (int u = 0; u < 2; u++){
        int off = u*8192 + tid*16;
        cp_async16(scr_smem + 16384 + off, (const char*)W1c + 16384 + off);
    }
    CP_COMMIT();

    // ---- small fills ----
    if (tid < 256){
        float a = clip50(slots_t[(b*Nn + i)*Dd + tid]);
        STIPu[tid] = pack2(a, a);
        AB[tid] = g_A[(b*Nn + i)*Dd + tid];
    } else if (tid < 320){
        W3S[tid - 256] = W3[tid - 256];
    } else if (tid < 384){
        B2S[tid - 320] = b2[tid - 320];
    }

    const u64 NEG1 = 0xBF800000BF800000ULL;
    const u64 ABSM = 0x7FFFFFFF7FFFFFFFULL;

    CP_WAIT2();          // ST1T resident
    __syncthreads();     // STIP/AB visible

    // ---- DD(0): DD[kk][j] = (|a-s|,|a-s|) duplicated ----
    {
        const int kk = tid >> 5, jp = tid & 31;
        u64 s2 = ST1Tu[kk*32 + jp];
        u64 a2 = STIPu[kk];
        u64 dp = fma2r(s2, NEG1, a2) & ABSM;
        float dlo, dhi; unpack2(dp, dlo, dhi);
        DDu[kk*64 + 2*jp    ] = pack2(dlo, dlo);
        DDu[kk*64 + 2*jp + 1] = pack2(dhi, dhi);
    }

    // ---- GEMM1 mainloop (16 tiles of K=16) ----
    u64 acc[4][4];
    #pragma unroll
    for (int p=0;p<4;p++)
        #pragma unroll
        for (int q=0;q<4;q++) acc[p][q] = 0ULL;

    for (int t = 0; t < 16; t++){
        if (t < 15) { CP_WAIT1(); } else { CP_WAIT0(); }
        __syncthreads();

        // build DD(t+1) into other buffer
        if (t < 15){
            const int kk = tid >> 5, jp = tid & 31;
            u64* DDn = DDu + ((t+1)&1)*1024;
            u64 s2 = ST1Tu[((t+1)*16 + kk)*32 + jp];
            u64 a2 = STIPu[(t+1)*16 + kk];
            u64 dp = fma2r(s2, NEG1, a2) & ABSM;
            float dlo, dhi; unpack2(dp, dlo, dhi);
            DDn[kk*64 + 2*jp    ] = pack2(dlo, dlo);
            DDn[kk*64 + 2*jp + 1] = pack2(dhi, dhi);
        }

        const u64* WS  = SCRu + (t&1)*2048;   // [16][128] u64
        const u64* DDb = DDu  + (t&1)*1024;   // [16][64] u64

        #pragma unroll 16
        for (int kk = 0; kk < 16; kk++){
            u64 w0 = WS[kk*128 + tx];
            u64 w1 = WS[kk*128 + tx + 32];
            u64 w2 = WS[kk*128 + tx + 64];
            u64 w3 = WS[kk*128 + tx + 96];
            u64 d0 = DDb[kk*64 + jb + 0];
            u64 d1 = DDb[kk*64 + jb + 1];
            u64 d2 = DDb[kk*64 + jb + 2];
            u64 d3 = DDb[kk*64 + jb + 3];
            fma2(acc[0][0], d0, w0); fma2(acc[0][1], d0, w1);
            fma2(acc[0][2], d0, w2); fma2(acc[0][3], d0, w3);
            fma2(acc[1][0], d1, w0); fma2(acc[1][1], d1, w1);
            fma2(acc[1][2], d1, w2); fma2(acc[1][3], d1, w3);
            fma2(acc[2][0], d2, w0); fma2(acc[2][1], d2, w1);
            fma2(acc[2][2], d2, w2); fma2(acc[2][3], d2, w3);
            fma2(acc[3][0], d3, w0); fma2(acc[3][1], d3, w1);
            fma2(acc[3][2], d3, w2); fma2(acc[3][3], d3, w3);
        }
        __syncthreads();
        if (t + 2 < 16){
            const int tn = t + 2;
            #pragma unroll
            for (int u = 0; u < 2; u++){
                int off = u*8192 + tid*16;
                cp_async16(scr_smem + (tn&1)*16384 + off, (const char*)W1c + tn*16384 + off);
            }
            CP_COMMIT();
        }
    }

    // ---- GEMM1 epilogue: add A_i + (Bm_j + b1), relu, write H ----
    #pragma unroll
    for (int p=0;p<4;p++){
        const int j = jb + p;
        #pragma unroll
        for (int q=0;q<4;q++){
            const int cpair = tx + 32*q;
            float2 ab = *reinterpret_cast<const float2*>(&AB[2*cpair]);
            float2 bm = *reinterpret_cast<const float2*>(&g_Bm[(b*Nn + j)*Dd + 2*cpair]);
            float lo, hi; unpack2(acc[p][q], lo, hi);
            float2 hv = make_float2(fmaxf(lo + ab.x + bm.x, 0.f),
                                    fmaxf(hi + ab.y + bm.y, 0.f));
            *reinterpret_cast<float2*>(&H[j*256 + 2*cpair]) = hv;
        }
    }
    __syncthreads();   // H ready; ST1T fully dead (all DD built)

    // ---- build W2 pair layout in ST1T region: W2P[kp][m] = (W2[2kp][m], W2[2kp+1][m]) ----
    u64* W2P = ST1Tu;
    #pragma unroll
    for (int n = 0; n < 16; n++){
        int idx = tid + n*512;
        int kp = idx >> 6, m = idx & 63;
        W2P[idx] = pack2(W2[(2*kp)*64 + m], W2[(2*kp + 1)*64 + m]);
    }
    __syncthreads();

    // ---- GEMM2: H2 = relu(H @ W2 + b2); warp w owns rows w*4..w*4+3 ----
    u64 acc2[4][2];
    #pragma unroll
    for (int rr=0;rr<4;rr++){ acc2[rr][0]=0ULL; acc2[rr][1]=0ULL; }

    #pragma unroll 8
    for (int kp = 0; kp < 128; kp++){
        u64 wp0 = W2P[kp*64 + tx];
        u64 wp1 = W2P[kp*64 + 32 + tx];
        #pragma unroll
        for (int rr=0;rr<4;rr++){
            u64 hp = lds64(&H[(jb+rr)*256 + 2*kp]);
            fma2(acc2[rr][0], hp, wp0);
            fma2(acc2[rr][1], hp, wp1);
        }
    }
    __syncthreads();   // SCR fully dead; reuse as H2

    float* H2 = sm + SOFF_SCR;   // [64][64]
    #pragma unroll
    for (int rr=0;rr<4;rr++){
        float lo, hi;
        unpack2(acc2[rr][0], lo, hi);
        H2[(jb+rr)*64 + tx     ] = fmaxf(lo + hi + B2S[tx     ], 0.f);
        unpack2(acc2[rr][1], lo, hi);
        H2[(jb+rr)*64 + tx + 32] = fmaxf(lo + hi + B2S[tx + 32], 0.f);
    }
    __syncthreads();

    // ---- GEMM3 + penalties + log_alpha ----
    {
        const int g = tx >> 3, l = tx & 7;
        const int j = w*4 + g;
        float4 hA = *reinterpret_cast<const float4*>(&H2[j*64 + l*8]);
        float4 hB = *reinterpret_cast<const float4*>(&H2[j*64 + l*8 + 4]);
        float4 wA = *reinterpret_cast<const float4*>(&W3S[l*8]);
        float4 wB = *reinterpret_cast<const float4*>(&W3S[l*8 + 4]);
        float s = hA.x*wA.x + hA.y*wA.y + hA.z*wA.z + hA.w*wA.w
                + hB.x*wB.x + hB.y*wB.y + hB.z*wB.z + hB.w*wB.w;
        s += __shfl_xor_sync(0xffffffffu, s, 4);
        s += __shfl_xor_sync(0xffffffffu, s, 2);
        s += __shfl_xor_sync(0xffffffffu, s, 1);
        if (l == 0){
            float score = s + b3[0];
            if (alive_t [b*Nn + i] < 0.5f) score -= PEN;
            if (alive_t1[b*Nn + j] < 0.5f) score -= PEN;
            float la = fminf(fmaxf(score, -PEN), PEN) * INV_TEMP;
            g_la[(b*Nn + i)*Nn + j] = la;
        }
    }
}

// ================= Kernel 3: Sinkhorn (20 iters) + argmax + matched ==============
__global__ void __launch_bounds__(512) sinkhorn_kernel(
    const float* __restrict__ alive_t, const float* __restrict__ alive_t1,
    float* __restrict__ out)
{
    __shared__ float la[64][65];
    const int b = blockIdx.x;
    const int tid = threadIdx.x;
    const int lane = tid & 31, w = tid >> 5;   // 16 warps

    for (int idx = tid; idx < 64*64; idx += 512)
        la[idx >> 6][idx & 63] = g_la[b*4096 + idx];
    __syncthreads();

    for (int it = 0; it < 20; it++){
        #pragma unroll
        for (int rr = 0; rr < 4; rr++){
            const int i = w*4 + rr;
            float v0 = la[i][lane], v1 = la[i][lane+32];
            float m = fmaxf(v0, v1);
            #pragma unroll
            for (int off = 16; off > 0; off >>= 1) m = fmaxf(m, __shfl_xor_sync(0xffffffffu, m, off));
            float s = expf(v0 - m) + expf(v1 - m);
            #pragma unroll
            for (int off = 16; off > 0; off >>= 1) s += __shfl_xor_sync(0xffffffffu, s, off);
            float lse = m + logf(s);
            la[i][lane]    = v0 - lse;
            la[i][lane+32] = v1 - lse;
        }
        __syncthreads();
        #pragma unroll
        for (int rr = 0; rr < 4; rr++){
            const int j = w*4 + rr;
            float v0 = la[lane][j], v1 = la[lane+32][j];
            float m = fmaxf(v0, v1);
            #pragma unroll
            for (int off = 16; off > 0; off >>= 1) m = fmaxf(m, __shfl_xor_sync(0xffffffffu, m, off));
            float s = expf(v0 - m) + expf(v1 - m);
            #pragma unroll
            for (int off = 16; off > 0; off >>= 1) s += __shfl_xor_sync(0xffffffffu, s, off);
            float lse = m + logf(s);
            la[lane][j]    = v0 - lse;
            la[lane+32][j] = v1 - lse;
        }
        __syncthreads();
    }

    #pragma unroll
    for (int rr = 0; rr < 4; rr++){
        const int i = w*4 + rr;
        float v0 = la[i][lane], v1 = la[i][lane+32];
        float bv; int bi;
        if (v1 > v0){ bv = v1; bi = lane + 32; } else { bv = v0; bi = lane; }
        #pragma unroll
        for (int off = 16; off > 0; off >>= 1){
            float ov = __shfl_xor_sync(0xffffffffu, bv, off);
            int   oi = __shfl_xor_sync(0xffffffffu, bi, off);
            if (ov > bv || (ov == bv && oi < bi)){ bv = ov; bi = oi; }
        }
        if (lane == 0){
            float conf = expf(bv);
            float at  = alive_t [b*Nn + i];
            float at1 = alive_t1[b*Nn + bi];
            float matched = (at > 0.5f && at1 > 0.5f && conf > 0.3f) ? 1.f : 0.f;
            out[b*Nn + i]           = (float)bi;   // perm
            out[Bb*Nn + b*Nn + i]   = matched;     // matched
        }
    }
}

// ================= launch =================
extern "C" void kernel_launch(void* const* d_in, const int* in_sizes, int n_in,
                              void* d_out, int out_size)
{
    const float* slots_t  = (const float*)d_in[0];
    const float* slots_t1 = (const float*)d_in[1];
    const float* alive_t  = (const float*)d_in[2];
    const float* alive_t1 = (const float*)d_in[3];
    const float* W1 = (const float*)d_in[4];
    const float* b1 = (const float*)d_in[5];
    const float* W2 = (const float*)d_in[6];
    const float* b2 = (const float*)d_in[7];
    const float* W3 = (const float*)d_in[8];
    const float* b3 = (const float*)d_in[9];
    float* out = (float*)d_out;

    cudaFuncSetAttribute(precompute_kernel, cudaFuncAttributeMaxDynamicSharedMemorySize, P_SMEM_BYTES);
    cudaFuncSetAttribute(score_kernel,      cudaFuncAttributeMaxDynamicSharedMemorySize, S_SMEM_BYTES);

    precompute_kernel<<<dim3(4, Bb), 512, P_SMEM_BYTES>>>(slots_t, slots_t1, W1, b1);
    score_kernel<<<dim3(Nn, Bb), 512, S_SMEM_BYTES>>>(slots_t, alive_t, alive_t1,
                                                      W1, W2, b2, W3, b3);
    sinkhorn_kernel<<<Bb, 512>>>(alive_t, alive_t1, out);
}